// round 10
// baseline (speedup 1.0000x reference)
#include <cuda_runtime.h>
#include <math.h>

#define BS 16
#define NA 8400
#define NG 128
#define NC 80
#define TOPK 13
#define CAPC 1024            // per-row candidate capacity (expected <=~530)

#define GRIDB 20             // bins per dim
#define BINW_INV (1.0f/32.0f)
#define NBINS (GRIDB*GRIDB)
#define MAXSEG 8             // max covered bin-rows (box <=144px -> <=6)

#define EPS9 1e-9f
#define EPS7 1e-7f
#define FOUR_OVER_PI2 0.4052847345693511f

// ---- scratch (__device__ globals; no allocation allowed) ----
// INVARIANT: g_bincnt == 0 at kernel_launch entry. True at process start
// (static zero-init) and restored at the end of every call by k4_final.
__device__ int                g_bincnt[NBINS];
__device__ int                g_binstart[NBINS + 1];
__device__ float4             g_csr[NA];                 // (ax, ay, idx_bits, 0)
__device__ int                g_firstg[BS * NA];         // min marked g (init BIG)
__device__ int                g_acnt  [BS * NA];         // mark count
__device__ unsigned long long g_bestpack[BS * NA];       // (al_bits<<32)|(127-g)
__device__ int                g_anyflag;

#define FIRSTG_INIT 0x40000000

// CIoU clipped to [0,inf); identical op order in KMAIN and K4.
__device__ __forceinline__ float ciou_clip(
    float b1x1, float b1y1, float b1x2, float b1y2,
    float b2x1, float b2y1, float b2x2, float b2y2)
{
    float iw = fminf(b1x2, b2x2) - fmaxf(b1x1, b2x1); iw = fmaxf(iw, 0.0f);
    float ih = fminf(b1y2, b2y2) - fmaxf(b1y1, b2y1); ih = fmaxf(ih, 0.0f);
    const float inter = iw * ih;
    const float w1 = b1x2 - b1x1, h1 = b1y2 - b1y1 + EPS7;
    const float w2 = b2x2 - b2x1, h2 = b2y2 - b2y1 + EPS7;
    const float uni = w1 * h1 + w2 * h2 - inter + EPS7;
    const float iou = inter / uni;
    const float cw = fmaxf(b1x2, b2x2) - fminf(b1x1, b2x1);
    const float ch = fmaxf(b1y2, b2y2) - fminf(b1y1, b2y1);
    const float c2 = cw * cw + ch * ch + EPS7;
    const float dx = b2x1 + b2x2 - b1x1 - b1x2;
    const float dy = b2y1 + b2y2 - b1y1 - b1y2;
    const float rho2 = (dx * dx + dy * dy) * 0.25f;
    const float dat = atanf(w2 / h2) - atanf(w1 / h1);
    const float v = FOUR_OVER_PI2 * dat * dat;
    const float alpha = v / (v - iou + (1.0f + EPS7));
    return fmaxf(iou - (rho2 / c2 + v * alpha), 0.0f);
}

__device__ __forceinline__ int bin_of(float x) {
    int b = (int)(x * BINW_INV);
    return (b < 0) ? 0 : ((b > GRIDB - 1) ? GRIDB - 1 : b);
}

// ============================================================
// K_COUNT: fully parallel: zero per-anchor state + anyflag;
// first NA threads also count anchors per bin via global
// atomics (g_bincnt is zero at entry per the invariant).
// ============================================================
#define CBLOCKS ((BS * NA + 1023) / 1024)     // 132 blocks

__global__ void kCount(const float* __restrict__ anc_points)
{
    const int i = blockIdx.x * 1024 + threadIdx.x;
    if (i < BS * NA) {
        g_firstg[i]   = FIRSTG_INIT;
        g_acnt[i]     = 0;
        g_bestpack[i] = 127ULL;     // pack(0.0f, g=0)
    }
    if (i == 0) g_anyflag = 0;
    if (i < NA) {
        const float2 p = reinterpret_cast<const float2*>(anc_points)[i];
        atomicAdd(&g_bincnt[bin_of(p.y) * GRIDB + bin_of(p.x)], 1);
    }
}

// ============================================================
// K_SCANFILL: one block. Warp 0: shuffle-scan over 400 bins
// (13 segments, no block barriers). Then 1024-thread CSR fill.
// ============================================================
__global__ void kScanFill(const float* __restrict__ anc_points)
{
    const int tid = threadIdx.x;   // 1024
    __shared__ int s_off[NBINS];

    if (tid < 32) {
        int run = 0;
        for (int base = 0; base < NBINS; base += 32) {
            const int idx = base + tid;
            const int cnt = (idx < NBINS) ? g_bincnt[idx] : 0;
            int inc = cnt;
#pragma unroll
            for (int off = 1; off < 32; off <<= 1) {
                const int n = __shfl_up_sync(0xffffffffu, inc, off);
                if (tid >= off) inc += n;
            }
            const int excl = run + inc - cnt;
            if (idx < NBINS) { g_binstart[idx] = excl; s_off[idx] = excl; }
            run += __shfl_sync(0xffffffffu, inc, 31);
        }
        if (tid == 0) g_binstart[NBINS] = run;
    }
    __syncthreads();

    for (int a = tid; a < NA; a += 1024) {
        const float2 p = reinterpret_cast<const float2*>(anc_points)[a];
        const int bin = bin_of(p.y) * GRIDB + bin_of(p.x);
        const int q = atomicAdd(&s_off[bin], 1);
        g_csr[q] = make_float4(p.x, p.y, __int_as_float(a), 0.0f);
    }
}

// ============================================================
// K_MAIN: one block (256 thr) per (b,g) row. Flattened segment
// gather, candidate collection in smem, warp-0 top-13
// (shuffle-only, lowest-index tie-break == lax.top_k), marks
// firstg/acnt/anyflag, best_gt via 64-bit atomicMax. All
// marking ops are order-invariant -> deterministic on replay.
// ============================================================
__global__ void kmain(const float* __restrict__ pd_scores,
                      const float* __restrict__ pd_bboxes,
                      const int*   __restrict__ gt_labels,
                      const float* __restrict__ gt_bboxes,
                      const float* __restrict__ gt_mask)
{
    const int row = blockIdx.x;          // b*NG + g
    const int tid = threadIdx.x;         // 256
    const int b = row >> 7;
    const int g = row & (NG - 1);

    __shared__ float s_cv[CAPC];
    __shared__ int   s_ci[CAPC];
    __shared__ int   s_cnt;
    __shared__ int   s_seg_s[MAXSEG];
    __shared__ int   s_seg_p[MAXSEG + 1];
    __shared__ float4 s_box;
    __shared__ float  s_msk;
    __shared__ int    s_lbl;

    if (tid == 0) {
        s_cnt = 0;
        s_box = reinterpret_cast<const float4*>(gt_bboxes)[(size_t)b * NG + g];
        s_msk = gt_mask[row];
        int l = gt_labels[row];
        s_lbl = (l < 0) ? 0 : ((l >= NC) ? NC - 1 : l);
        // build flattened segment table
        const float4 bb = s_box;
        const int bx0 = bin_of(bb.x), bx1 = bin_of(bb.z);
        const int by0 = bin_of(bb.y), by1 = bin_of(bb.w);
        int acc = 0, ns = 0;
        for (int by = by0; by <= by1 && ns < MAXSEG; by++, ns++) {
            const int s = g_binstart[by * GRIDB + bx0];
            const int e = g_binstart[by * GRIDB + bx1 + 1];
            s_seg_s[ns] = s;
            s_seg_p[ns] = acc;
            acc += e - s;
        }
        for (int k2 = ns; k2 <= MAXSEG; k2++) s_seg_p[k2] = acc;
    }
    __syncthreads();

    const float msk = s_msk;
    if (msk <= 0.0f) return;

    const float4 gbb = s_box;
    const int lbl = s_lbl;
    const int total = s_seg_p[MAXSEG];

    for (int t = tid; t < total; t += 256) {
        int r = 0;
#pragma unroll
        for (int k2 = 1; k2 < MAXSEG; k2++)
            if (t >= s_seg_p[k2]) r = k2;
        const int j = s_seg_s[r] + (t - s_seg_p[r]);

        const float4 ent = g_csr[j];
        const float ax = ent.x, ay = ent.y;
        const float d0 = ax - gbb.x, d1 = ay - gbb.y;
        const float d2 = gbb.z - ax, d3 = gbb.w - ay;
        const float dmin = fminf(fminf(d0, d1), fminf(d2, d3));
        if (dmin > EPS9) {
            const int a = __float_as_int(ent.z);
            const float4 pb = reinterpret_cast<const float4*>(pd_bboxes)[(size_t)b * NA + a];
            const float io = ciou_clip(pb.x, pb.y, pb.z, pb.w,
                                       gbb.x, gbb.y, gbb.z, gbb.w);
            const float sc = pd_scores[((size_t)b * NA + a) * NC + lbl];
            const float i2 = io * io;
            const float al = sc * (i2 * i2 * i2) * msk;
            if (al > 0.0f) {
                const unsigned long long pk =
                    ((unsigned long long)__float_as_uint(al) << 32) |
                    (unsigned long long)(127 - g);
                atomicMax(&g_bestpack[b * NA + a], pk);
            }
            if (al > EPS9) {
                const int p = atomicAdd(&s_cnt, 1);
                if (p < CAPC) { s_cv[p] = al; s_ci[p] = a; }
            }
        }
    }
    __syncthreads();

    if (tid >= 32) return;               // warps 1..7 done; warp 0 does top-k

    int cnt = s_cnt;
    if (cnt > CAPC) cnt = CAPC;
    const int kmax = (TOPK < cnt) ? TOPK : cnt;

    for (int k = 0; k < kmax; k++) {
        float bv = -1.0f; int bix = 0x7fffffff; int bslot = -1;
        for (int i = tid; i < cnt; i += 32) {
            const float v  = s_cv[i];
            const int   ix = s_ci[i];
            if (v > bv || (v == bv && ix < bix)) { bv = v; bix = ix; bslot = i; }
        }
#pragma unroll
        for (int off = 16; off > 0; off >>= 1) {
            const float ov = __shfl_down_sync(0xffffffffu, bv, off);
            const int oix  = __shfl_down_sync(0xffffffffu, bix, off);
            const int osl  = __shfl_down_sync(0xffffffffu, bslot, off);
            if (ov > bv || (ov == bv && oix < bix)) { bv = ov; bix = oix; bslot = osl; }
        }
        bslot = __shfl_sync(0xffffffffu, bslot, 0);
        if (tid == 0 && bslot >= 0) {     // value guaranteed > EPS9
            const int a = s_ci[bslot];
            atomicMin(&g_firstg[b * NA + a], g);
            const int old = atomicAdd(&g_acnt[b * NA + a], 1);
            if (old > 0) g_anyflag = 1;
            s_cv[bslot] = -1.0f;
        }
        __syncwarp();
    }
}

// ============================================================
// K4: per-anchor resolution + ALL outputs (fused; score write
// via smem staging, streaming stores). Also restores the
// g_bincnt == 0 invariant for the next call.
// ============================================================
__global__ void k4_final(const int*   __restrict__ gt_labels,
                         const float* __restrict__ gt_bboxes,
                         const float* __restrict__ pd_bboxes,
                         const float* __restrict__ pd_scores,
                         const float* __restrict__ anc_points,
                         const float* __restrict__ gt_mask,
                         float* __restrict__ out)
{
    const int tid = threadIdx.x;                       // 256
    const int i   = blockIdx.x * 256 + tid;            // exact grid
    const int b   = i / NA;
    const int a   = i - b * NA;

    if (i < NBINS) g_bincnt[i] = 0;    // restore invariant (counts consumed)

    const int flag = g_anyflag;
    const int conf = (g_acnt[i] > 1);
    const int best = 127 - (int)(g_bestpack[i] & 0xFFULL);
    const int fg   = g_firstg[i];
    const int g0   = (fg >= FIRSTG_INIT) ? -1 : fg;

    int gA = -1, gB = -1; float vA = 0.0f, vB = 0.0f;
    if (flag) {
        if (!conf) {
            if (g0 < 0)          { gA = best; vA = 1.0f; }
            else if (g0 == best) { gA = g0;   vA = 2.0f; }
            else if (g0 < best)  { gA = g0; vA = 1.0f; gB = best; vB = 1.0f; }
            else                 { gA = best; vA = 1.0f; gB = g0; vB = 1.0f; }
        }
    } else {
        if (g0 >= 0) { gA = g0; vA = 1.0f; }
    }

    int tgt = 0;
    const int anyv = (gA >= 0);
    if (gA >= 0) tgt = gA;

    float maxamf = 0.0f, maxiou = 0.0f;
    if (anyv) {
        const float4 pb = reinterpret_cast<const float4*>(pd_bboxes)[(size_t)b * NA + a];
        const float ax = anc_points[a * 2 + 0];
        const float ay = anc_points[a * 2 + 1];
#pragma unroll
        for (int c = 0; c < 2; c++) {
            const int gc = (c == 0) ? gA : gB;
            const float vc = (c == 0) ? vA : vB;
            if (gc < 0) continue;
            const float4 gbb = reinterpret_cast<const float4*>(gt_bboxes)[(size_t)b * NG + gc];
            const float io = ciou_clip(pb.x, pb.y, pb.z, pb.w, gbb.x, gbb.y, gbb.z, gbb.w);
            int l = gt_labels[(size_t)b * NG + gc];
            l = (l < 0) ? 0 : ((l >= NC) ? NC - 1 : l);
            const float sc = pd_scores[((size_t)b * NA + a) * NC + l];
            const float d0 = ax - gbb.x, d1 = ay - gbb.y;
            const float d2 = gbb.z - ax, d3 = gbb.w - ay;
            const float dmin = fminf(fminf(d0, d1), fminf(d2, d3));
            const float mp = (dmin > EPS9) ? gt_mask[(size_t)b * NG + gc] : 0.0f;
            const float i2 = io * io;
            const float al = sc * (i2 * i2 * i2) * mp;
            maxamf = fmaxf(maxamf, al * vc);
            maxiou = fmaxf(maxiou, io * vc);
        }
    }
    const float norm = (maxamf * maxamf) / (maxiou + 1e-9f);
    const int   cls  = gt_labels[(size_t)b * NG + tgt];

    const size_t N1 = (size_t)BS * NA;
    out[i] = (float)cls;
    reinterpret_cast<float4*>(out + N1)[i] =
        reinterpret_cast<const float4*>(gt_bboxes)[(size_t)b * NG + tgt];
    const size_t off_mask = N1 * 5 + N1 * (size_t)NC;
    out[off_mask + i]      = anyv ? 1.0f : 0.0f;
    out[off_mask + N1 + i] = norm;

    // coalesced one-hot score write via smem staging; streaming stores
    __shared__ int   s_cls[256];
    __shared__ float s_nrm[256];
    s_cls[tid] = cls;
    s_nrm[tid] = norm;
    __syncthreads();
    float4* sco4 = reinterpret_cast<float4*>(out + N1 * 5 + (size_t)blockIdx.x * 256 * NC);
    for (int idx = tid; idx < 256 * (NC / 4); idx += 256) {
        const int al = idx / (NC / 4);
        const int q  = idx - al * (NC / 4);
        const int c0 = q * 4;
        const int cl = s_cls[al];
        const float nv = s_nrm[al];
        float4 w = make_float4(0.0f, 0.0f, 0.0f, 0.0f);
        if (cl == c0)     w.x = nv;
        if (cl == c0 + 1) w.y = nv;
        if (cl == c0 + 2) w.z = nv;
        if (cl == c0 + 3) w.w = nv;
        __stcs(sco4 + idx, w);
    }
}

// ============================================================
extern "C" void kernel_launch(void* const* d_in, const int* in_sizes, int n_in,
                              void* d_out, int out_size)
{
    const float* pd_scores = (const float*)d_in[0];
    const float* pd_bboxes = (const float*)d_in[1];
    const float* anc       = (const float*)d_in[2];
    const int*   gl        = (const int*)d_in[3];
    const float* gb        = (const float*)d_in[4];
    const float* gm        = (const float*)d_in[5];
    float* out = (float*)d_out;

    kCount<<<CBLOCKS, 1024>>>(anc);
    kScanFill<<<1, 1024>>>(anc);
    kmain<<<BS * NG, 256>>>(pd_scores, pd_bboxes, gl, gb, gm);
    k4_final<<<(BS * NA) / 256, 256>>>(gl, gb, pd_bboxes, pd_scores, anc, gm, out);
}

// round 11
// speedup vs baseline: 1.6037x; 1.6037x over previous
#include <cuda_runtime.h>
#include <math.h>

#define BS 16
#define NA 8400
#define NG 128
#define NC 80
#define TOPK 13
#define CAPC 1024            // per-row candidate capacity (expected <=~530)

#define GRIDB 20             // bins per dim
#define BINW_INV (1.0f/32.0f)
#define NBINS (GRIDB*GRIDB)
#define MAXSEG 8             // max covered bin-rows (box <=144px -> <=6)

#define EPS9 1e-9f
#define EPS7 1e-7f
#define FOUR_OVER_PI2 0.4052847345693511f

// ---- scratch (__device__ globals; no allocation allowed) ----
__device__ int                g_binstart[NBINS + 1];
__device__ int                g_csridx[NA];              // anchor index per CSR slot
__device__ int                g_firstg[BS * NA];         // min marked g (init BIG)
__device__ int                g_acnt  [BS * NA];         // mark count
__device__ unsigned long long g_bestpack[BS * NA];       // (al_bits<<32)|(127-g)
__device__ int                g_anyflag;

#define FIRSTG_INIT 0x40000000

// CIoU clipped to [0,inf); identical op order in KMAIN and K4.
__device__ __forceinline__ float ciou_clip(
    float b1x1, float b1y1, float b1x2, float b1y2,
    float b2x1, float b2y1, float b2x2, float b2y2)
{
    float iw = fminf(b1x2, b2x2) - fmaxf(b1x1, b2x1); iw = fmaxf(iw, 0.0f);
    float ih = fminf(b1y2, b2y2) - fmaxf(b1y1, b2y1); ih = fmaxf(ih, 0.0f);
    const float inter = iw * ih;
    const float w1 = b1x2 - b1x1, h1 = b1y2 - b1y1 + EPS7;
    const float w2 = b2x2 - b2x1, h2 = b2y2 - b2y1 + EPS7;
    const float uni = w1 * h1 + w2 * h2 - inter + EPS7;
    const float iou = inter / uni;
    const float cw = fmaxf(b1x2, b2x2) - fminf(b1x1, b2x1);
    const float ch = fmaxf(b1y2, b2y2) - fminf(b1y1, b2y1);
    const float c2 = cw * cw + ch * ch + EPS7;
    const float dx = b2x1 + b2x2 - b1x1 - b1x2;
    const float dy = b2y1 + b2y2 - b1y1 - b1y2;
    const float rho2 = (dx * dx + dy * dy) * 0.25f;
    const float dat = atanf(w2 / h2) - atanf(w1 / h1);
    const float v = FOUR_OVER_PI2 * dat * dat;
    const float alpha = v / (v - iou + (1.0f + EPS7));
    return fmaxf(iou - (rho2 / c2 + v * alpha), 0.0f);
}

__device__ __forceinline__ int bin_of(float x) {
    int b = (int)(x * BINW_INV);
    return (b < 0) ? 0 : ((b > GRIDB - 1) ? GRIDB - 1 : b);
}

// ============================================================
// K_SETUP: block 0 does binning (count -> 2-level scan -> fill);
// blocks >= 1 zero per-anchor state + anyflag. Disjoint writes.
// ============================================================
#define ZBLOCKS ((BS * NA + 1023) / 1024)     // 132 zeroing blocks
#define SCAN_WARPS ((NBINS + 31) / 32)        // 13

__global__ void kSetup(const float* __restrict__ anc_points)
{
    const int tid = threadIdx.x;   // 1024

    if (blockIdx.x > 0) {
        const int i = (blockIdx.x - 1) * 1024 + tid;
        if (i < BS * NA) {
            g_firstg[i]   = FIRSTG_INIT;
            g_acnt[i]     = 0;
            g_bestpack[i] = 127ULL;     // pack(0.0f, g=0)
        }
        if (blockIdx.x == 1 && tid == 0) g_anyflag = 0;
        return;
    }

    __shared__ int s_cnt[NBINS];
    __shared__ int s_off[NBINS];
    __shared__ int s_wsum[SCAN_WARPS];

    for (int i = tid; i < NBINS; i += 1024) s_cnt[i] = 0;
    __syncthreads();

    for (int a = tid; a < NA; a += 1024) {
        const float2 p = reinterpret_cast<const float2*>(anc_points)[a];
        atomicAdd(&s_cnt[bin_of(p.y) * GRIDB + bin_of(p.x)], 1);
    }
    __syncthreads();

    // two-level exclusive scan over NBINS=400 (13 warps in parallel)
    const int wid  = tid >> 5;
    const int lane = tid & 31;
    int cnt = 0, inc = 0;
    if (tid < ((SCAN_WARPS) * 32)) {
        cnt = (tid < NBINS) ? s_cnt[tid] : 0;
        inc = cnt;
#pragma unroll
        for (int off = 1; off < 32; off <<= 1) {
            const int n = __shfl_up_sync(0xffffffffu, inc, off);
            if (lane >= off) inc += n;
        }
        if (lane == 31) s_wsum[wid] = inc;
    }
    __syncthreads();
    if (wid == 0) {
        int ws = (lane < SCAN_WARPS) ? s_wsum[lane] : 0;
        int wi = ws;
#pragma unroll
        for (int off = 1; off < 32; off <<= 1) {
            const int n = __shfl_up_sync(0xffffffffu, wi, off);
            if (lane >= off) wi += n;
        }
        if (lane < SCAN_WARPS) s_wsum[lane] = wi - ws;   // exclusive warp offset
    }
    __syncthreads();
    if (tid < NBINS) {
        const int excl = (inc - cnt) + s_wsum[wid];
        g_binstart[tid] = excl;
        s_off[tid] = excl;
    }
    if (tid == 0) g_binstart[NBINS] = NA;
    __syncthreads();

    for (int a = tid; a < NA; a += 1024) {
        const float2 p = reinterpret_cast<const float2*>(anc_points)[a];
        const int bin = bin_of(p.y) * GRIDB + bin_of(p.x);
        const int q = atomicAdd(&s_off[bin], 1);
        g_csridx[q] = a;
    }
}

// ============================================================
// K_MAIN: one block (256 thr) per (b,g) row. Flattened segment
// gather, candidate collection in smem, warp-0 top-13
// (shuffle-only, lowest-index tie-break == lax.top_k), marks
// firstg/acnt/anyflag, best_gt via 64-bit atomicMax. All
// marking ops are order-invariant -> deterministic on replay.
// ============================================================
__global__ void kmain(const float* __restrict__ pd_scores,
                      const float* __restrict__ pd_bboxes,
                      const int*   __restrict__ gt_labels,
                      const float* __restrict__ gt_bboxes,
                      const float* __restrict__ gt_mask,
                      const float* __restrict__ anc_points)
{
    const int row = blockIdx.x;          // b*NG + g
    const int tid = threadIdx.x;         // 256
    const int b = row >> 7;
    const int g = row & (NG - 1);

    __shared__ float s_cv[CAPC];
    __shared__ int   s_ci[CAPC];
    __shared__ int   s_cnt;
    __shared__ int   s_seg_s[MAXSEG];
    __shared__ int   s_seg_p[MAXSEG + 1];
    __shared__ float4 s_box;
    __shared__ float  s_msk;
    __shared__ int    s_lbl;

    if (tid == 0) {
        s_cnt = 0;
        s_box = reinterpret_cast<const float4*>(gt_bboxes)[(size_t)b * NG + g];
        s_msk = gt_mask[row];
        int l = gt_labels[row];
        s_lbl = (l < 0) ? 0 : ((l >= NC) ? NC - 1 : l);
        // build flattened segment table
        const float4 bb = s_box;
        const int bx0 = bin_of(bb.x), bx1 = bin_of(bb.z);
        const int by0 = bin_of(bb.y), by1 = bin_of(bb.w);
        int acc = 0, ns = 0;
        for (int by = by0; by <= by1 && ns < MAXSEG; by++, ns++) {
            const int s = g_binstart[by * GRIDB + bx0];
            const int e = g_binstart[by * GRIDB + bx1 + 1];
            s_seg_s[ns] = s;
            s_seg_p[ns] = acc;
            acc += e - s;
        }
        for (int k2 = ns; k2 <= MAXSEG; k2++) s_seg_p[k2] = acc;
    }
    __syncthreads();

    const float msk = s_msk;
    if (msk <= 0.0f) return;

    const float4 gbb = s_box;
    const int lbl = s_lbl;
    const int total = s_seg_p[MAXSEG];
    const float2* anc2 = reinterpret_cast<const float2*>(anc_points);

    for (int t = tid; t < total; t += 256) {
        int r = 0;
#pragma unroll
        for (int k2 = 1; k2 < MAXSEG; k2++)
            if (t >= s_seg_p[k2]) r = k2;
        const int j = s_seg_s[r] + (t - s_seg_p[r]);

        const int a = g_csridx[j];
        const float2 p = anc2[a];
        const float d0 = p.x - gbb.x, d1 = p.y - gbb.y;
        const float d2 = gbb.z - p.x, d3 = gbb.w - p.y;
        const float dmin = fminf(fminf(d0, d1), fminf(d2, d3));
        if (dmin > EPS9) {
            const float4 pb = reinterpret_cast<const float4*>(pd_bboxes)[(size_t)b * NA + a];
            const float io = ciou_clip(pb.x, pb.y, pb.z, pb.w,
                                       gbb.x, gbb.y, gbb.z, gbb.w);
            const float sc = pd_scores[((size_t)b * NA + a) * NC + lbl];
            const float i2 = io * io;
            const float al = sc * (i2 * i2 * i2) * msk;
            if (al > 0.0f) {
                const unsigned long long pk =
                    ((unsigned long long)__float_as_uint(al) << 32) |
                    (unsigned long long)(127 - g);
                atomicMax(&g_bestpack[b * NA + a], pk);
            }
            if (al > EPS9) {
                const int pIdx = atomicAdd(&s_cnt, 1);
                if (pIdx < CAPC) { s_cv[pIdx] = al; s_ci[pIdx] = a; }
            }
        }
    }
    __syncthreads();

    if (tid >= 32) return;               // warps 1..7 done; warp 0 does top-k

    int cnt = s_cnt;
    if (cnt > CAPC) cnt = CAPC;
    const int kmax = (TOPK < cnt) ? TOPK : cnt;

    for (int k = 0; k < kmax; k++) {
        float bv = -1.0f; int bix = 0x7fffffff; int bslot = -1;
        for (int i = tid; i < cnt; i += 32) {
            const float v  = s_cv[i];
            const int   ix = s_ci[i];
            if (v > bv || (v == bv && ix < bix)) { bv = v; bix = ix; bslot = i; }
        }
#pragma unroll
        for (int off = 16; off > 0; off >>= 1) {
            const float ov = __shfl_down_sync(0xffffffffu, bv, off);
            const int oix  = __shfl_down_sync(0xffffffffu, bix, off);
            const int osl  = __shfl_down_sync(0xffffffffu, bslot, off);
            if (ov > bv || (ov == bv && oix < bix)) { bv = ov; bix = oix; bslot = osl; }
        }
        bslot = __shfl_sync(0xffffffffu, bslot, 0);
        if (tid == 0 && bslot >= 0) {     // value guaranteed > EPS9
            const int a = s_ci[bslot];
            atomicMin(&g_firstg[b * NA + a], g);
            const int old = atomicAdd(&g_acnt[b * NA + a], 1);
            if (old > 0) g_anyflag = 1;
            s_cv[bslot] = -1.0f;
        }
        __syncwarp();
    }
}

// ============================================================
// K4: per-anchor resolution + ALL outputs (fused; score write
// via smem staging, streaming stores).
// ============================================================
__global__ void k4_final(const int*   __restrict__ gt_labels,
                         const float* __restrict__ gt_bboxes,
                         const float* __restrict__ pd_bboxes,
                         const float* __restrict__ pd_scores,
                         const float* __restrict__ anc_points,
                         const float* __restrict__ gt_mask,
                         float* __restrict__ out)
{
    const int tid = threadIdx.x;                       // 256
    const int i   = blockIdx.x * 256 + tid;            // exact grid
    const int b   = i / NA;
    const int a   = i - b * NA;

    const int flag = g_anyflag;
    const int conf = (g_acnt[i] > 1);
    const int best = 127 - (int)(g_bestpack[i] & 0xFFULL);
    const int fg   = g_firstg[i];
    const int g0   = (fg >= FIRSTG_INIT) ? -1 : fg;

    int gA = -1, gB = -1; float vA = 0.0f, vB = 0.0f;
    if (flag) {
        if (!conf) {
            if (g0 < 0)          { gA = best; vA = 1.0f; }
            else if (g0 == best) { gA = g0;   vA = 2.0f; }
            else if (g0 < best)  { gA = g0; vA = 1.0f; gB = best; vB = 1.0f; }
            else                 { gA = best; vA = 1.0f; gB = g0; vB = 1.0f; }
        }
    } else {
        if (g0 >= 0) { gA = g0; vA = 1.0f; }
    }

    int tgt = 0;
    const int anyv = (gA >= 0);
    if (gA >= 0) tgt = gA;

    float maxamf = 0.0f, maxiou = 0.0f;
    if (anyv) {
        const float4 pb = reinterpret_cast<const float4*>(pd_bboxes)[(size_t)b * NA + a];
        const float ax = anc_points[a * 2 + 0];
        const float ay = anc_points[a * 2 + 1];
#pragma unroll
        for (int c = 0; c < 2; c++) {
            const int gc = (c == 0) ? gA : gB;
            const float vc = (c == 0) ? vA : vB;
            if (gc < 0) continue;
            const float4 gbb = reinterpret_cast<const float4*>(gt_bboxes)[(size_t)b * NG + gc];
            const float io = ciou_clip(pb.x, pb.y, pb.z, pb.w, gbb.x, gbb.y, gbb.z, gbb.w);
            int l = gt_labels[(size_t)b * NG + gc];
            l = (l < 0) ? 0 : ((l >= NC) ? NC - 1 : l);
            const float sc = pd_scores[((size_t)b * NA + a) * NC + l];
            const float d0 = ax - gbb.x, d1 = ay - gbb.y;
            const float d2 = gbb.z - ax, d3 = gbb.w - ay;
            const float dmin = fminf(fminf(d0, d1), fminf(d2, d3));
            const float mp = (dmin > EPS9) ? gt_mask[(size_t)b * NG + gc] : 0.0f;
            const float i2 = io * io;
            const float al = sc * (i2 * i2 * i2) * mp;
            maxamf = fmaxf(maxamf, al * vc);
            maxiou = fmaxf(maxiou, io * vc);
        }
    }
    const float norm = (maxamf * maxamf) / (maxiou + 1e-9f);
    const int   cls  = gt_labels[(size_t)b * NG + tgt];

    const size_t N1 = (size_t)BS * NA;
    out[i] = (float)cls;
    reinterpret_cast<float4*>(out + N1)[i] =
        reinterpret_cast<const float4*>(gt_bboxes)[(size_t)b * NG + tgt];
    const size_t off_mask = N1 * 5 + N1 * (size_t)NC;
    out[off_mask + i]      = anyv ? 1.0f : 0.0f;
    out[off_mask + N1 + i] = norm;

    // coalesced one-hot score write via smem staging; streaming stores
    __shared__ int   s_cls[256];
    __shared__ float s_nrm[256];
    s_cls[tid] = cls;
    s_nrm[tid] = norm;
    __syncthreads();
    float4* sco4 = reinterpret_cast<float4*>(out + N1 * 5 + (size_t)blockIdx.x * 256 * NC);
    for (int idx = tid; idx < 256 * (NC / 4); idx += 256) {
        const int al = idx / (NC / 4);
        const int q  = idx - al * (NC / 4);
        const int c0 = q * 4;
        const int cl = s_cls[al];
        const float nv = s_nrm[al];
        float4 w = make_float4(0.0f, 0.0f, 0.0f, 0.0f);
        if (cl == c0)     w.x = nv;
        if (cl == c0 + 1) w.y = nv;
        if (cl == c0 + 2) w.z = nv;
        if (cl == c0 + 3) w.w = nv;
        __stcs(sco4 + idx, w);
    }
}

// ============================================================
extern "C" void kernel_launch(void* const* d_in, const int* in_sizes, int n_in,
                              void* d_out, int out_size)
{
    const float* pd_scores = (const float*)d_in[0];
    const float* pd_bboxes = (const float*)d_in[1];
    const float* anc       = (const float*)d_in[2];
    const int*   gl        = (const int*)d_in[3];
    const float* gb        = (const float*)d_in[4];
    const float* gm        = (const float*)d_in[5];
    float* out = (float*)d_out;

    kSetup<<<1 + ZBLOCKS, 1024>>>(anc);
    kmain<<<BS * NG, 256>>>(pd_scores, pd_bboxes, gl, gb, gm, anc);
    k4_final<<<(BS * NA) / 256, 256>>>(gl, gb, pd_bboxes, pd_scores, anc, gm, out);
}